// round 8
// baseline (speedup 1.0000x reference)
#include <cuda_runtime.h>

#define WIRE_DIM 32
#define NUM_WIRES 64
#define ROW_ELEMS (NUM_WIRES * WIRE_DIM)   // 2048
#define HALF_PAD 36                         // wire stride in smem floats (conflict-free float4)
#define ROWS_PER_BLOCK 4
#define THREADS (32 * ROWS_PER_BLOCK)

__global__ __launch_bounds__(THREADS, 8)
void isinone_loss_kernel(const float* __restrict__ outputs,
                         const int* __restrict__ tests,      // int32 pairs (person, location)
                         const float* __restrict__ W1,
                         const float* __restrict__ b1,
                         const float* __restrict__ W2,
                         const float* __restrict__ b2,
                         float* __restrict__ out,
                         int B)
{
    // W1 bottom rows transposed: s_w1b[h*32 + k] = W1[(32+k)*10 + h]
    __shared__ __align__(16) float s_w1b[10 * 32];
    // W1 top rows, original layout: s_w1top[k*10 + h] = W1[k*10 + h]  (conflict-free lane reads)
    __shared__ __align__(16) float s_w1top[320];
    // half-row staging buffer: 32 wires x pad36, reused for both halves
    __shared__ __align__(16) float s_half[ROWS_PER_BLOCK][32 * HALF_PAD];
    __shared__ float s_w2[10];
    __shared__ float s_b2;
    __shared__ float s_aw[ROWS_PER_BLOCK][10];   // b1 + person_vec @ W1_top, per warp/row

    const int tid = threadIdx.x;

    // ---- load weights (once per block) ----
    for (int i = tid; i < 320; i += THREADS) {
        s_w1top[i] = W1[i];                    // straight copy of first 32 rows
        int h = i >> 5, k = i & 31;
        s_w1b[h * 32 + k] = W1[(32 + k) * 10 + h];
    }
    if (tid < 10) s_w2[tid] = W2[tid];
    if (tid == 0) s_b2 = b2[0];
    __syncthreads();

    const int warp = tid >> 5;
    const int lane = tid & 31;
    const int row  = blockIdx.x * ROWS_PER_BLOCK + warp;
    if (row >= B) return;

    const float*  grow  = outputs + (size_t)row * ROW_ELEMS;
    const float4* grow4 = (const float4*)grow;
    float* sh = s_half[warp];

    const int p   = tests[2 * row + 0];
    const int loc = tests[2 * row + 1];

    // ---- pass 1 staging: wires 0..31 (coalesced LDG.128 -> conflict-free STS.128) ----
#pragma unroll
    for (int i = 0; i < 8; i++) {
        int j = i * 32 + lane;                 // float4 index 0..255
        float4 v = grow4[j];
        *(float4*)&sh[(j >> 3) * HALF_PAD + ((j & 7) << 2)] = v;
    }

    // ---- person projection (lanes 0..9, uniform-address gmem reads, overlaps staging) ----
    if (lane < 10) {
        float aw = b1[lane];
        const float* pv = grow + p * WIRE_DIM;
#pragma unroll
        for (int k = 0; k < WIRE_DIM; k++)
            aw = fmaf(pv[k], s_w1top[k * 10 + lane], aw);
        s_aw[warp][lane] = aw;
    }
    __syncwarp();

    // ---- pass 1 MLP: lane handles wire = lane ----
    float acc[10];
#pragma unroll
    for (int h = 0; h < 10; h++) acc[h] = 0.f;
    const float4* rA = (const float4*)&sh[lane * HALF_PAD];
#pragma unroll
    for (int g = 0; g < 8; g++) {
        float4 v = rA[g];
#pragma unroll
        for (int h = 0; h < 10; h++) {
            float4 w = *(const float4*)&s_w1b[h * 32 + g * 4];   // broadcast
            acc[h] = fmaf(v.x, w.x, acc[h]);
            acc[h] = fmaf(v.y, w.y, acc[h]);
            acc[h] = fmaf(v.z, w.z, acc[h]);
            acc[h] = fmaf(v.w, w.w, acc[h]);
        }
    }
    float l0 = s_b2;
#pragma unroll
    for (int h = 0; h < 10; h++)
        l0 = fmaf(fmaxf(acc[h] + s_aw[warp][h], 0.f), s_w2[h], l0);

    __syncwarp();   // all pass-1 LDS consumed before buffer reuse

    // ---- pass 2 staging: wires 32..63 into the same buffer ----
#pragma unroll
    for (int i = 0; i < 8; i++) {
        int j = 256 + i * 32 + lane;           // float4 index 256..511
        float4 v = grow4[j];
        *(float4*)&sh[((j >> 3) - 32) * HALF_PAD + ((j & 7) << 2)] = v;
    }
    __syncwarp();

    // ---- pass 2 MLP: lane handles wire = lane + 32 ----
#pragma unroll
    for (int h = 0; h < 10; h++) acc[h] = 0.f;
#pragma unroll
    for (int g = 0; g < 8; g++) {
        float4 v = rA[g];
#pragma unroll
        for (int h = 0; h < 10; h++) {
            float4 w = *(const float4*)&s_w1b[h * 32 + g * 4];   // broadcast
            acc[h] = fmaf(v.x, w.x, acc[h]);
            acc[h] = fmaf(v.y, w.y, acc[h]);
            acc[h] = fmaf(v.z, w.z, acc[h]);
            acc[h] = fmaf(v.w, w.w, acc[h]);
        }
    }
    float l1 = s_b2;
#pragma unroll
    for (int h = 0; h < 10; h++)
        l1 = fmaf(fmaxf(acc[h] + s_aw[warp][h], 0.f), s_w2[h], l1);

    // ---- warp log-softmax over 64 logits (2 per lane) ----
    float m = fmaxf(l0, l1);
#pragma unroll
    for (int o = 16; o; o >>= 1) m = fmaxf(m, __shfl_xor_sync(0xffffffffu, m, o));
    float s = __expf(l0 - m) + __expf(l1 - m);
#pragma unroll
    for (int o = 16; o; o >>= 1) s += __shfl_xor_sync(0xffffffffu, s, o);
    float lse = m + __logf(s);

    float lsel = __shfl_sync(0xffffffffu, (loc < 32) ? l0 : l1, loc & 31);
    if (lane == 0) out[row] = lse - lsel;   // loss = -(logit[loc] - lse)
}

extern "C" void kernel_launch(void* const* d_in, const int* in_sizes, int n_in,
                              void* d_out, int out_size)
{
    const float* outputs = (const float*)d_in[0];
    const int*   tests   = (const int*)d_in[1];
    const float* W1      = (const float*)d_in[2];
    const float* b1      = (const float*)d_in[3];
    const float* W2      = (const float*)d_in[4];
    const float* b2      = (const float*)d_in[5];
    float* out = (float*)d_out;

    const int B = in_sizes[0] / ROW_ELEMS;
    const int grid = (B + ROWS_PER_BLOCK - 1) / ROWS_PER_BLOCK;
    isinone_loss_kernel<<<grid, THREADS>>>(outputs, tests, W1, b1, W2, b2, out, B);
}

// round 11
// speedup vs baseline: 1.2092x; 1.2092x over previous
#include <cuda_runtime.h>
#include <cstdint>

#define WIRE_DIM 32
#define NUM_WIRES 64
#define ROW_ELEMS (NUM_WIRES * WIRE_DIM)   // 2048
#define ROW_PAD 36                          // wire stride in smem floats (conflict-free LDS.128, 16B-aligned)
#define ROWS_PER_BLOCK 4
#define THREADS (32 * ROWS_PER_BLOCK)

// packed fp32x2 FMA (SASS FFMA2) — d = a*b + c elementwise on (lo,hi)
#define FMA_F32X2(d, a, b, c) \
    asm("fma.rn.f32x2 %0, %1, %2, %3;" : "=l"(d) : "l"(a), "l"(b), "l"(c))

__device__ __forceinline__ uint64_t pk2(float lo, float hi) {
    uint64_t r; asm("mov.b64 %0, {%1, %2};" : "=l"(r) : "f"(lo), "f"(hi)); return r;
}
__device__ __forceinline__ float2 upk2(uint64_t v) {
    float2 r; asm("mov.b64 {%0, %1}, %2;" : "=f"(r.x), "=f"(r.y) : "l"(v)); return r;
}

__global__ __launch_bounds__(THREADS)
void isinone_loss_kernel(const float* __restrict__ outputs,
                         const int* __restrict__ tests,      // int32 pairs (person, location)
                         const float* __restrict__ W1,
                         const float* __restrict__ b1,
                         const float* __restrict__ W2,
                         const float* __restrict__ b2,
                         float* __restrict__ out,
                         int B)
{
    // W1 bottom rows transposed, k-contiguous per h: s_w1b[h*32 + k] = W1[(32+k)*10 + h]
    __shared__ __align__(16) float s_w1b[10 * 32];
    // W1 top rows, original [k][h] layout (conflict-free lane reads for person proj)
    __shared__ __align__(16) float s_w1top[320];
    __shared__ __align__(16) float s_wires[ROWS_PER_BLOCK][NUM_WIRES * ROW_PAD];
    __shared__ float s_w2[10];
    __shared__ float s_b2;
    __shared__ float s_aw[ROWS_PER_BLOCK][10];   // b1 + person_vec @ W1_top

    const int tid = threadIdx.x;

    // ---- load weights (once per block) ----
    for (int i = tid; i < 320; i += THREADS) {
        s_w1top[i] = W1[i];                    // first 32 rows, as-is
        int h = i >> 5, k = i & 31;
        s_w1b[h * 32 + k] = W1[(32 + k) * 10 + h];
    }
    if (tid < 10) s_w2[tid] = W2[tid];
    if (tid == 0) s_b2 = b2[0];
    __syncthreads();

    const int warp = tid >> 5;
    const int lane = tid & 31;
    const int row  = blockIdx.x * ROWS_PER_BLOCK + warp;
    if (row >= B) return;

    const float*  grow  = outputs + (size_t)row * ROW_ELEMS;
    const float4* grow4 = (const float4*)grow;
    float* srow = s_wires[warp];

    const int p   = tests[2 * row + 0];
    const int loc = tests[2 * row + 1];

    // ---- stage full row gmem -> smem (coalesced LDG.128 -> conflict-free STS.128) ----
#pragma unroll
    for (int i = 0; i < 16; i++) {
        int j = i * 32 + lane;                 // float4 index 0..511
        float4 v = grow4[j];
        *(float4*)&srow[(j >> 3) * ROW_PAD + ((j & 7) << 2)] = v;
    }

    // ---- person projection (lanes 0..9, uniform gmem reads overlap staging) ----
    if (lane < 10) {
        float aw = b1[lane];
        const float* pv = grow + p * WIRE_DIM;
#pragma unroll
        for (int k = 0; k < WIRE_DIM; k++)
            aw = fmaf(pv[k], s_w1top[k * 10 + lane], aw);
        s_aw[warp][lane] = aw;
    }
    __syncwarp();

    // ---- main MLP, packed f32x2 across the k dimension ----
    // lane handles wires (lane) and (lane+32)
    uint64_t acc0[10], acc1[10];
#pragma unroll
    for (int h = 0; h < 10; h++) {
        float a = s_aw[warp][h];
        acc0[h] = pk2(a, 0.f);                 // fold person+bias into lo half
        acc1[h] = pk2(a, 0.f);
    }

    const ulonglong2* rA = (const ulonglong2*)&srow[lane * ROW_PAD];         // 2 packed pairs / LDS.128
    const ulonglong2* rB = (const ulonglong2*)&srow[(lane + 32) * ROW_PAD];
#pragma unroll
    for (int g = 0; g < 8; g++) {
        ulonglong2 va = rA[g];                 // k = 4g..4g+3 of wire lane
        ulonglong2 vb = rB[g];
#pragma unroll
        for (int h = 0; h < 10; h++) {
            ulonglong2 w = *(const ulonglong2*)&s_w1b[h * 32 + g * 4];       // broadcast LDS.128
            FMA_F32X2(acc0[h], va.x, w.x, acc0[h]);
            FMA_F32X2(acc0[h], va.y, w.y, acc0[h]);
            FMA_F32X2(acc1[h], vb.x, w.x, acc1[h]);
            FMA_F32X2(acc1[h], vb.y, w.y, acc1[h]);
        }
    }

    // ---- head: h = relu(lo + hi), logits ----
    float l0 = s_b2, l1 = s_b2;
#pragma unroll
    for (int h = 0; h < 10; h++) {
        float2 a0 = upk2(acc0[h]);
        float2 a1 = upk2(acc1[h]);
        l0 = fmaf(fmaxf(a0.x + a0.y, 0.f), s_w2[h], l0);
        l1 = fmaf(fmaxf(a1.x + a1.y, 0.f), s_w2[h], l1);
    }

    // ---- warp log-softmax over 64 logits (2 per lane) ----
    float m = fmaxf(l0, l1);
#pragma unroll
    for (int o = 16; o; o >>= 1) m = fmaxf(m, __shfl_xor_sync(0xffffffffu, m, o));
    float s = __expf(l0 - m) + __expf(l1 - m);
#pragma unroll
    for (int o = 16; o; o >>= 1) s += __shfl_xor_sync(0xffffffffu, s, o);
    float lse = m + __logf(s);

    float lsel = __shfl_sync(0xffffffffu, (loc < 32) ? l0 : l1, loc & 31);
    if (lane == 0) out[row] = lse - lsel;   // loss = -(logit[loc] - lse)
}

extern "C" void kernel_launch(void* const* d_in, const int* in_sizes, int n_in,
                              void* d_out, int out_size)
{
    const float* outputs = (const float*)d_in[0];
    const int*   tests   = (const int*)d_in[1];
    const float* W1      = (const float*)d_in[2];
    const float* b1      = (const float*)d_in[3];
    const float* W2      = (const float*)d_in[4];
    const float* b2      = (const float*)d_in[5];
    float* out = (float*)d_out;

    const int B = in_sizes[0] / ROW_ELEMS;
    const int grid = (B + ROWS_PER_BLOCK - 1) / ROWS_PER_BLOCK;
    isinone_loss_kernel<<<grid, THREADS>>>(outputs, tests, W1, b1, W2, b2, out, B);
}